// round 2
// baseline (speedup 1.0000x reference)
#include <cuda_runtime.h>
#include <math.h>

// MT 1D forward + loss. Output: [total_loss, loss_rhoa, loss_phase] (3 x f32).
//
// Scaled Moebius recursion: per-layer matrix divided by 2*Zj so eigenvalues
// are {1, -e} (|e|<=1) -> no systematic scale drift, no divides in loop.
//   A' = p/2,  B' = Zj*q/2,  C' = q/(2*Zj),  p=1-e, q=1+e, e=exp(-(1+i)a)
//   N' = A'N + B'D,  D' = C'N + A'D,  Z = N/D  (ratio invariant under scaling)
// Renormalize every 16 steps to kill the zero-mean scale random walk.

#define MUF 1.25663706143591729e-6f   // 4*pi*1e-7
#define TWO_PI_F 6.2831853071795864f
#define RAD2DEG_F 57.295779513082321f

__device__ float2 g_part[256];

__device__ __forceinline__ float frcp_fast(float x) {
    float r;
    asm("rcp.approx.ftz.f32 %0, %1;" : "=f"(r) : "f"(x));
    return r;
}

// L = (coef, 0.5*c1, 0.25/c1, pad);  coef = t*sqrt(2*mu/rho), c1 = sqrt(0.5*mu*rho)
__device__ __forceinline__ void mt_step(float4 L, float s, float invs,
                                        float& Nr, float& Ni,
                                        float& Dr, float& Di)
{
    float a  = s * L.x;                 // attenuation argument (>= 0, <= ~14)
    float em = __expf(-a);
    float sa, ca;
    __sincosf(a, &sa, &ca);
    float er = em * ca;                 // e = er - i*ei
    float ei = em * sa;

    float Apr = 0.5f - 0.5f * er;       // A' = p/2
    float Api = 0.5f * ei;
    float qr  = 1.0f + er;
    float t1  = qr + ei;
    float t2  = qr - ei;
    float u   = s * L.y;                // zr/2
    float Br  = u * t1;                 // B' = Zj*q/2
    float Bi  = u * t2;
    float v   = invs * L.z;             // 1/(4*zr)
    float Cr  = v * t2;                 // C' = q/(2*Zj)
    float Ci  = -v * t1;

    float nNr = Apr * Nr - Api * Ni + Br * Dr - Bi * Di;
    float nNi = Apr * Ni + Api * Nr + Br * Di + Bi * Dr;
    float nDr = Cr  * Nr - Ci  * Ni + Apr * Dr - Api * Di;
    float nDi = Cr  * Ni + Ci  * Nr + Apr * Di + Api * Dr;
    Nr = nNr; Ni = nNi; Dr = nDr; Di = nDi;
}

__global__ __launch_bounds__(256, 1)
void mt_main(const float* __restrict__ res,
             const float* __restrict__ thick,
             const float* __restrict__ freq,
             const float* __restrict__ orhoa,
             const float* __restrict__ ophase,
             int nz, int nf)
{
    __shared__ float4 lay[512];    // scan order (deepest first)
    __shared__ float  sc_last;
    __shared__ float2 red[8];

    const int nl  = nz - 1;
    const int tid = threadIdx.x;

    for (int i = tid; i < nl; i += blockDim.x) {
        int   j   = nl - 1 - i;                 // deepest layer first
        float rho = res[j];
        float t   = thick[j];
        float c1  = sqrtf(0.5f * MUF * rho);
        lay[i] = make_float4(t * sqrtf(2.0f * MUF / rho),
                             0.5f * c1,
                             0.25f / c1,
                             0.0f);
    }
    if (tid == 0) sc_last = sqrtf(0.5f * MUF * res[nz - 1]);
    __syncthreads();

    int   f  = blockIdx.x * blockDim.x + tid;
    float lr = 0.0f, lp = 0.0f;

    if (f < nf) {
        float omega = TWO_PI_F * freq[f];
        float s     = sqrtf(omega);
        float invs  = rsqrtf(omega);
        float wmu   = omega * MUF;

        // Z0 = s*c1_last*(1+i);  N = Z0, D = 1
        float Nr = s * sc_last, Ni = Nr;
        float Dr = 1.0f, Di = 0.0f;

        int i = 0;
        for (; i + 16 <= nl; i += 16) {
            #pragma unroll
            for (int u = 0; u < 16; ++u)
                mt_step(lay[i + u], s, invs, Nr, Ni, Dr, Di);
            // kill residual scale random walk (ratio N/D is invariant)
            float m = frcp_fast(fabsf(Nr) + fabsf(Ni) + fabsf(Dr) + fabsf(Di));
            Nr *= m; Ni *= m; Dr *= m; Di *= m;
        }
        for (; i < nl; ++i)
            mt_step(lay[i], s, invs, Nr, Ni, Dr, Di);

        // Z = N/D (full-precision divide, once per thread)
        float d2  = Dr * Dr + Di * Di;
        float Zr  = (Nr * Dr + Ni * Di) / d2;
        float Zi  = (Ni * Dr - Nr * Di) / d2;

        float app = (Zr * Zr + Zi * Zi) / wmu;
        float ph  = atan2f(Zi, Zr) * RAD2DEG_F;

        float e1 = log10f(app) - log10f(orhoa[f]);
        float e2 = ph - ophase[f];
        lr = e1 * e1;
        lp = e2 * e2;
    }

    // deterministic block reduction
    const unsigned FULL = 0xffffffffu;
    #pragma unroll
    for (int o = 16; o > 0; o >>= 1) {
        lr += __shfl_down_sync(FULL, lr, o);
        lp += __shfl_down_sync(FULL, lp, o);
    }
    int wid = tid >> 5, lane = tid & 31;
    if (lane == 0) red[wid] = make_float2(lr, lp);
    __syncthreads();
    if (tid < 32) {
        float2 v = (tid < (int)(blockDim.x >> 5)) ? red[tid]
                                                  : make_float2(0.0f, 0.0f);
        lr = v.x; lp = v.y;
        #pragma unroll
        for (int o = 4; o > 0; o >>= 1) {
            lr += __shfl_down_sync(FULL, lr, o);
            lp += __shfl_down_sync(FULL, lp, o);
        }
        if (tid == 0) g_part[blockIdx.x] = make_float2(lr, lp);
    }
}

__global__ void mt_finish(float* __restrict__ out, int nblocks, float inv_nf)
{
    int t = threadIdx.x;
    float lr = 0.0f, lp = 0.0f;
    for (int i = t; i < nblocks; i += 32) {
        float2 v = g_part[i];
        lr += v.x; lp += v.y;
    }
    const unsigned FULL = 0xffffffffu;
    #pragma unroll
    for (int o = 16; o > 0; o >>= 1) {
        lr += __shfl_down_sync(FULL, lr, o);
        lp += __shfl_down_sync(FULL, lp, o);
    }
    if (t == 0) {
        float mlr = lr * inv_nf;
        float mlp = lp * inv_nf;
        out[0] = mlr + 10.0f * mlp;   // LAMBDA_RHOA=1, LAMBDA_PHASE=10
        out[1] = mlr;
        out[2] = mlp;
    }
}

extern "C" void kernel_launch(void* const* d_in, const int* in_sizes, int n_in,
                              void* d_out, int out_size)
{
    const float* res = (const float*)d_in[0];
    const float* th  = (const float*)d_in[1];
    const float* fr  = (const float*)d_in[2];
    const float* orh = (const float*)d_in[3];
    const float* oph = (const float*)d_in[4];
    int nz = in_sizes[0];
    int nf = in_sizes[2];

    const int threads = 256;
    int blocks = (nf + threads - 1) / threads;     // 64 for NF=16384
    if (blocks > 256) blocks = 256;

    mt_main<<<blocks, threads>>>(res, th, fr, orh, oph, nz, nf);
    mt_finish<<<1, 32>>>((float*)d_out, blocks, 1.0f / (float)nf);
}

// round 4
// speedup vs baseline: 1.5229x; 1.5229x over previous
#include <cuda_runtime.h>
#include <math.h>

// MT 1D forward + loss, fused single kernel. Output: [total, loss_rhoa, loss_phase].
//
// Diagonalized Moebius recursion in the U=N+D, V=N-D basis with per-layer
// impedance normalization x = Z/Zj:
//   U' = alpha*U - beta*(E*V),  V' = beta*U - alpha*(E*V)
//   alpha = g+1, beta = g-1, g = sqrt(rho_j / rho_{j-1})   (real, precomputed)
//   E = exp(-a)*(cos a - i sin a),  a = s*coef_j,  coef_j = t_j*sqrt(2*mu/rho_j)
// Final: x = N/D = (U+V)/(U-V);  app_res = rho_0*|x|^2;
//   phase = atan2(A+B, A-B), A = Nr*Dr+Ni*Di, B = Ni*Dr-Nr*Di (no division).

#define MUF 1.25663706143591729e-6f   // 4*pi*1e-7
#define TWO_PI_F 6.2831853071795864f
#define RAD2DEG_F 57.295779513082321f

__device__ float2 g_part[256];
__device__ unsigned int g_ticket;     // zero-init; reset by last block each launch

__device__ __forceinline__ float frcp_fast(float x) {
    float r;
    asm("rcp.approx.ftz.f32 %0, %1;" : "=f"(r) : "f"(x));
    return r;
}

// L = (coef_j, alpha, beta, pad)
__device__ __forceinline__ void mt_step(float4 L, float s,
                                        float& Ur, float& Ui,
                                        float& Vr, float& Vi)
{
    float a  = s * L.x;
    float em = __expf(-a);
    float sa, ca;
    __sincosf(a, &sa, &ca);
    float er = em * ca;                 // E = er - i*ei
    float ei = em * sa;

    // w = E*V
    float wr = er * Vr + ei * Vi;
    float wi = er * Vi - ei * Vr;

    float al = L.y, be = L.z;
    float nUr = al * Ur - be * wr;
    float nUi = al * Ui - be * wi;
    float nVr = be * Ur - al * wr;
    float nVi = be * Ui - al * wi;
    Ur = nUr; Ui = nUi; Vr = nVr; Vi = nVi;
}

__global__ __launch_bounds__(128, 1)
void mt_fused(const float* __restrict__ res,
              const float* __restrict__ thick,
              const float* __restrict__ freq,
              const float* __restrict__ orhoa,
              const float* __restrict__ ophase,
              float* __restrict__ out,
              int nz, int nf, float inv_nf)
{
    __shared__ float4 lay[512];        // scan order (deepest layer first)
    __shared__ float  sc_x0, sc_lrho0;
    __shared__ float2 red[4];
    __shared__ int    is_last;

    const int nl  = nz - 1;
    const int tid = threadIdx.x;

    for (int i = tid; i < nl; i += blockDim.x) {
        int   j     = nl - 1 - i;                   // deepest first
        float rho   = res[j];
        float t     = thick[j];
        float g     = (j >= 1) ? sqrtf(rho / res[j - 1]) : 1.0f;
        lay[i] = make_float4(t * sqrtf(2.0f * MUF / rho),
                             g + 1.0f,
                             g - 1.0f,
                             0.0f);
    }
    if (tid == 0) {
        sc_x0    = sqrtf(res[nz - 1] / res[nz - 2]);  // x_init (real)
        sc_lrho0 = log10f(res[0]);
    }
    __syncthreads();

    int   f  = blockIdx.x * blockDim.x + tid;
    float lr = 0.0f, lp = 0.0f;

    if (f < nf) {
        float omega = TWO_PI_F * freq[f];
        float s     = sqrtf(omega);

        float x0 = sc_x0;
        float Ur = x0 + 1.0f, Ui = 0.0f;
        float Vr = x0 - 1.0f, Vi = 0.0f;

        int i = 0;
        for (; i + 8 <= nl; i += 8) {
            #pragma unroll
            for (int u = 0; u < 8; ++u)
                mt_step(lay[i + u], s, Ur, Ui, Vr, Vi);
            // renormalize: the (U,V) scale grows ~prod(alpha); ratio invariant
            float m = frcp_fast(fabsf(Ur) + fabsf(Ui) + fabsf(Vr) + fabsf(Vi));
            Ur *= m; Ui *= m; Vr *= m; Vi *= m;
        }
        for (; i < nl; ++i)
            mt_step(lay[i], s, Ur, Ui, Vr, Vi);

        float Nr = Ur + Vr, Ni = Ui + Vi;
        float Dr = Ur - Vr, Di = Ui - Vi;

        float n2 = fmaxf(Nr * Nr + Ni * Ni, 1e-30f);
        float d2 = fmaxf(Dr * Dr + Di * Di, 1e-30f);
        float A  = Nr * Dr + Ni * Di;
        float B  = Ni * Dr - Nr * Di;

        // app_res = rho0 * n2 / d2 ; Z ∝ (A-B) + i(A+B) (positive scale)
        float e1 = sc_lrho0 + log10f(n2) - log10f(d2) - log10f(orhoa[f]);
        float ph = atan2f(A + B, A - B) * RAD2DEG_F;
        float e2 = ph - ophase[f];
        lr = e1 * e1;
        lp = e2 * e2;
    }

    // deterministic block reduction (128 threads = 4 warps)
    const unsigned FULL = 0xffffffffu;
    #pragma unroll
    for (int o = 16; o > 0; o >>= 1) {
        lr += __shfl_down_sync(FULL, lr, o);
        lp += __shfl_down_sync(FULL, lp, o);
    }
    int wid = tid >> 5, lane = tid & 31;
    if (lane == 0) red[wid] = make_float2(lr, lp);
    __syncthreads();
    if (tid == 0) {
        float slr = red[0].x + red[1].x + red[2].x + red[3].x;
        float slp = red[0].y + red[1].y + red[2].y + red[3].y;
        g_part[blockIdx.x] = make_float2(slr, slp);
        __threadfence();
        unsigned t = atomicAdd(&g_ticket, 1u);
        is_last = (t == gridDim.x - 1) ? 1 : 0;
    }
    __syncthreads();

    if (is_last) {
        // last block reduces all partials (fixed order => deterministic)
        __threadfence();
        float flr = 0.0f, flp = 0.0f;
        if (tid < 32) {
            for (int i = tid; i < (int)gridDim.x; i += 32) {
                volatile float* vp = (volatile float*)&g_part[i];
                flr += vp[0];
                flp += vp[1];
            }
            #pragma unroll
            for (int o = 16; o > 0; o >>= 1) {
                flr += __shfl_down_sync(FULL, flr, o);
                flp += __shfl_down_sync(FULL, flp, o);
            }
            if (tid == 0) {
                float mlr = flr * inv_nf;
                float mlp = flp * inv_nf;
                out[0] = mlr + 10.0f * mlp;   // LAMBDA_RHOA=1, LAMBDA_PHASE=10
                out[1] = mlr;
                out[2] = mlp;
                g_ticket = 0;                 // reset for next graph replay
            }
        }
    }
}

extern "C" void kernel_launch(void* const* d_in, const int* in_sizes, int n_in,
                              void* d_out, int out_size)
{
    const float* res = (const float*)d_in[0];
    const float* th  = (const float*)d_in[1];
    const float* fr  = (const float*)d_in[2];
    const float* orh = (const float*)d_in[3];
    const float* oph = (const float*)d_in[4];
    int nz = in_sizes[0];
    int nf = in_sizes[2];

    const int threads = 128;
    int blocks = (nf + threads - 1) / threads;     // 128 for NF=16384
    if (blocks > 256) blocks = 256;

    mt_fused<<<blocks, threads>>>(res, th, fr, orh, oph,
                                  (float*)d_out, nz, nf, 1.0f / (float)nf);
}